// round 13
// baseline (speedup 1.0000x reference)
#include <cuda_runtime.h>
#include <cuda_bf16.h>
#include <math.h>
#include <stdint.h>

#define BATCH 1024
#define NJ 24
#define NV 6890
#define NVP 6912             // 27*256 padded verts
#define M_TOT 20670          // NV*3
#define M_PAD 20672          // row stride for v_posed
#define K_TOT 224
#define KP 256               // padded K stride for bf16 operand storage
#define M_WPAD 20736         // 162*128, padded rows of W

#define BM 128               // batch tile (main gemm)
#define BN 128               // m tile (main gemm)
#define NCH 7                // 7 * 32 = 224 K-chunks
#define SMEM_MMA 65536       // 2 stages x (16KB A + 16KB B)

#define NB 16                // batches per skin block
#define WBLK2 2592           // prep blocks for W conv (M_WPAD*32/256)
#define WSBLK 108            // prep blocks for skin-weight conv (NVP*4/256)

__constant__ int c_par[NJ] = {-1,0,0,0,1,2,3,4,5,6,7,8,9,9,9,12,13,14,16,17,18,19,20,21};

// Scratch (device globals -- no runtime allocation allowed)
__device__ float g_G2[BATCH * NJ * 12];
__device__ float g_Jv[NJ * 3];
__device__ float g_Js[NJ * 30];
__device__ float g_vposed[(size_t)BATCH * M_PAD + 1024];
__device__ __nv_bfloat16 g_Xhi[BATCH * KP];
__device__ __nv_bfloat16 g_Xlo[BATCH * KP];
__device__ __nv_bfloat16 g_Whi[(size_t)M_WPAD * KP];
__device__ __nv_bfloat16 g_Wlo[(size_t)M_WPAD * KP];
__device__ __nv_bfloat16 g_WShi[NVP * 32];   // skin weights hi, rows padded K=32
__device__ __nv_bfloat16 g_WSlo[NVP * 32];   // skin weights lo

// ---------------------------------------------------------------------------
// helpers
// ---------------------------------------------------------------------------
__device__ __forceinline__ uint32_t smem_u32(const void* p) {
    uint32_t a;
    asm("{ .reg .u64 t; cvta.to.shared.u64 t, %1; cvt.u32.u64 %0, t; }" : "=r"(a) : "l"(p));
    return a;
}
__device__ __forceinline__ void sts128(uint32_t a, uint4 v) {
    asm volatile("st.shared.v4.b32 [%0], {%1,%2,%3,%4};"
                 :: "r"(a), "r"(v.x), "r"(v.y), "r"(v.z), "r"(v.w) : "memory");
}
#define SWZ(o) ((o) ^ (((o) >> 3) & 0x70))
#define SWZ64(o) ((o) ^ (((o) >> 3) & 0x30))

#define CPASYNC16(sm, gp) \
    asm volatile("cp.async.cg.shared.global [%0], [%1], 16;" :: "r"(sm), "l"(gp) : "memory")
#define CPCOMMIT() asm volatile("cp.async.commit_group;" ::: "memory")
#define CPWAIT(n)  asm volatile("cp.async.wait_group %0;" :: "n"(n) : "memory")

#define LDSM_X4(R, ADDR) \
    asm volatile("ldmatrix.sync.aligned.m8n8.x4.shared.b16 {%0,%1,%2,%3}, [%4];" \
        : "=r"((R)[0]), "=r"((R)[1]), "=r"((R)[2]), "=r"((R)[3]) : "r"(ADDR))

#define LDSM_X2(R, ADDR) \
    asm volatile("ldmatrix.sync.aligned.m8n8.x2.shared.b16 {%0,%1}, [%2];" \
        : "=r"((R)[0]), "=r"((R)[1]) : "r"(ADDR))

#define MMA_BF16(C, A, B) \
    asm volatile("mma.sync.aligned.m16n8k16.row.col.f32.bf16.bf16.f32 " \
        "{%0,%1,%2,%3},{%4,%5,%6,%7},{%8,%9},{%0,%1,%2,%3};" \
        : "+f"((C)[0]), "+f"((C)[1]), "+f"((C)[2]), "+f"((C)[3]) \
        : "r"((A)[0]), "r"((A)[1]), "r"((A)[2]), "r"((A)[3]), "r"((B)[0]), "r"((B)[1]))

#define MMA_BF16P(C, A, b0, b1) \
    asm volatile("mma.sync.aligned.m16n8k16.row.col.f32.bf16.bf16.f32 " \
        "{%0,%1,%2,%3},{%4,%5,%6,%7},{%8,%9},{%0,%1,%2,%3};" \
        : "+f"((C)[0]), "+f"((C)[1]), "+f"((C)[2]), "+f"((C)[3]) \
        : "r"((A)[0]), "r"((A)[1]), "r"((A)[2]), "r"((A)[3]), "r"(b0), "r"(b1))

#define MMA_BF16_K8(C, A, B) \
    asm volatile("mma.sync.aligned.m16n8k8.row.col.f32.bf16.bf16.f32 " \
        "{%0,%1,%2,%3},{%4,%5},{%6},{%0,%1,%2,%3};" \
        : "+f"((C)[0]), "+f"((C)[1]), "+f"((C)[2]), "+f"((C)[3]) \
        : "r"((A)[0]), "r"((A)[1]), "r"(B))

// ---------------------------------------------------------------------------
// bf16 hi/lo pack
// ---------------------------------------------------------------------------
__device__ __forceinline__ void pack8(const float* v, uint4* hi4, uint4* lo4) {
    uint32_t hi[4], lo[4];
#pragma unroll
    for (int i = 0; i < 4; i++) {
        __nv_bfloat16 h0 = __float2bfloat16(v[2 * i]);
        __nv_bfloat16 h1 = __float2bfloat16(v[2 * i + 1]);
        __nv_bfloat16 l0 = __float2bfloat16(v[2 * i] - __bfloat162float(h0));
        __nv_bfloat16 l1 = __float2bfloat16(v[2 * i + 1] - __bfloat162float(h1));
        hi[i] = ((uint32_t)__bfloat16_as_ushort(h1) << 16) | __bfloat16_as_ushort(h0);
        lo[i] = ((uint32_t)__bfloat16_as_ushort(l1) << 16) | __bfloat16_as_ushort(l0);
    }
    *hi4 = make_uint4(hi[0], hi[1], hi[2], hi[3]);
    *lo4 = make_uint4(lo[0], lo[1], lo[2], lo[3]);
}

// ---------------------------------------------------------------------------
// Kernel 0 (prep): W conv + skin-weight conv + per-joint J-regressor reduce,
// all independent, one grid.
// ---------------------------------------------------------------------------
__global__ void __launch_bounds__(256) k_prep(const float* __restrict__ pd,
                                              const float* __restrict__ sd,
                                              const float* __restrict__ vt,
                                              const float* __restrict__ wts,
                                              const float* __restrict__ Jreg) {
    int bid = blockIdx.x;
    int t = threadIdx.x;
    if (bid < WBLK2) {
        int idx = bid * 256 + t;          // over M_WPAD*32
        int m = idx >> 5;
        int k0 = (idx & 31) * 8;
        float v[8];
#pragma unroll
        for (int i = 0; i < 8; i++) {
            int k = k0 + i;
            float x = 0.f;
            if (m < M_TOT) {
                if (k < 207)       x = pd[(size_t)m * 207 + k];
                else if (k < 217)  x = sd[(size_t)m * 10 + (k - 207)];
                else if (k == 217) x = vt[m];
            }
            v[i] = x;
        }
        uint4 hi4, lo4;
        pack8(v, &hi4, &lo4);
        size_t off = (size_t)idx * 8;
        *(uint4*)(g_Whi + off) = hi4;
        *(uint4*)(g_Wlo + off) = lo4;
    } else if (bid < WBLK2 + WSBLK) {
        int idx = (bid - WBLK2) * 256 + t;  // over NVP*4
        int vv = idx >> 2;
        int k0 = (idx & 3) * 8;
        float v[8];
#pragma unroll
        for (int i = 0; i < 8; i++) {
            int k = k0 + i;
            v[i] = (vv < NV && k < 24) ? wts[vv * 24 + k] : 0.f;
        }
        uint4 hi4, lo4;
        pack8(v, &hi4, &lo4);
        size_t off = (size_t)idx * 8;
        *(uint4*)(g_WShi + off) = hi4;
        *(uint4*)(g_WSlo + off) = lo4;
    } else {
        // one block per joint: full reduction over all verts
        int j = bid - WBLK2 - WSBLK;
        float acc[33];
#pragma unroll
        for (int e = 0; e < 33; e++) acc[e] = 0.f;
        for (int v = t; v < NV; v += 256) {
            float r = Jreg[j * NV + v];
            const float* vp = vt + v * 3;
            acc[0] += r * vp[0];
            acc[1] += r * vp[1];
            acc[2] += r * vp[2];
            const float* sp = sd + (size_t)v * 30;
#pragma unroll
            for (int e = 0; e < 30; e++) acc[3 + e] += r * sp[e];
        }
#pragma unroll
        for (int e = 0; e < 33; e++) {
#pragma unroll
            for (int o = 16; o > 0; o >>= 1)
                acc[e] += __shfl_xor_sync(0xffffffffu, acc[e], o);
        }
        __shared__ float part[8][33];
        int w = t >> 5, ln = t & 31;
        if (ln == 0) {
#pragma unroll
            for (int e = 0; e < 33; e++) part[w][e] = acc[e];
        }
        __syncthreads();
        if (t < 33) {
            float r = 0.f;
#pragma unroll
            for (int ww = 0; ww < 8; ww++) r += part[ww][t];
            if (t < 3) g_Jv[j * 3 + t] = r;
            else       g_Js[j * 30 + (t - 3)] = r;
        }
    }
}

// ---------------------------------------------------------------------------
// Kernel 1: Rodrigues + kinematic chain + G2 + jtr; writes X as bf16 hi/lo.
// ---------------------------------------------------------------------------
__device__ __forceinline__ void wr_xsplit(int idx, float v) {
    __nv_bfloat16 h = __float2bfloat16(v);
    g_Xhi[idx] = h;
    g_Xlo[idx] = __float2bfloat16(v - __bfloat162float(h));
}

__global__ void k_pose(const float* __restrict__ pose,
                       const float* __restrict__ betas,
                       const float* __restrict__ trans,
                       float* __restrict__ jtr) {
    int b = blockIdx.x, t = threadIdx.x;
    __shared__ float Rsh[NJ][9];
    __shared__ float Jsh[NJ][3];
    __shared__ float G[NJ][16];

    if (t < NJ) {
        float ax = pose[b * 72 + t * 3 + 0];
        float ay = pose[b * 72 + t * 3 + 1];
        float az = pose[b * 72 + t * 3 + 2];
        float th = sqrtf(ax * ax + ay * ay + az * az + 1e-8f);
        float inv = 1.f / th;
        float kx = ax * inv, ky = ay * inv, kz = az * inv;
        float ct = cosf(th), st = sinf(th);
        float K[9] = {0.f, -kz, ky, kz, 0.f, -kx, -ky, kx, 0.f};
        float Rm[9];
#pragma unroll
        for (int r = 0; r < 3; r++) {
#pragma unroll
            for (int c = 0; c < 3; c++) {
                float k2 = K[r * 3 + 0] * K[0 + c] + K[r * 3 + 1] * K[3 + c] + K[r * 3 + 2] * K[6 + c];
                Rm[r * 3 + c] = ((r == c) ? 1.f : 0.f) + st * K[r * 3 + c] + (1.f - ct) * k2;
            }
        }
#pragma unroll
        for (int e = 0; e < 9; e++) Rsh[t][e] = Rm[e];
        if (t >= 1) {
#pragma unroll
            for (int e = 0; e < 9; e++)
                wr_xsplit(b * KP + (t - 1) * 9 + e,
                          Rm[e] - ((e == 0 || e == 4 || e == 8) ? 1.f : 0.f));
        }
#pragma unroll
        for (int c = 0; c < 3; c++) {
            float v = g_Jv[t * 3 + c];
#pragma unroll
            for (int s = 0; s < 10; s++)
                v += g_Js[t * 30 + c * 10 + s] * betas[b * 10 + s];
            Jsh[t][c] = v;
        }
    }
    if (t < 17) {
        float v = (t < 10) ? betas[b * 10 + t] : ((t == 10) ? 1.f : 0.f);
        wr_xsplit(b * KP + 207 + t, v);
    }
    {
        int k = 224 + t;                 // zero tail 224..255
        g_Xhi[b * KP + k] = __float2bfloat16(0.f);
        g_Xlo[b * KP + k] = __float2bfloat16(0.f);
    }
    __syncwarp();

    if (t < 16) {
        int r = t >> 2, c = t & 3;
        G[0][t] = (r < 3) ? ((c < 3) ? Rsh[0][r * 3 + c] : Jsh[0][r])
                          : ((c == 3) ? 1.f : 0.f);
    }
    __syncwarp();

    for (int i = 1; i < NJ; i++) {
        int p = c_par[i];
        float v = 0.f;
        if (t < 16) {
            int r = t >> 2, c = t & 3;
            float l0, l1, l2, l3;
            if (c < 3) {
                l0 = Rsh[i][c]; l1 = Rsh[i][3 + c]; l2 = Rsh[i][6 + c]; l3 = 0.f;
            } else {
                l0 = Jsh[i][0] - Jsh[p][0];
                l1 = Jsh[i][1] - Jsh[p][1];
                l2 = Jsh[i][2] - Jsh[p][2];
                l3 = 1.f;
            }
            v = G[p][r * 4 + 0] * l0 + G[p][r * 4 + 1] * l1 +
                G[p][r * 4 + 2] * l2 + G[p][r * 4 + 3] * l3;
        }
        __syncwarp();
        if (t < 16) G[i][t] = v;
        __syncwarp();
    }

    if (t < NJ) {
        const float* g = G[t];
        float jx = Jsh[t][0], jy = Jsh[t][1], jz = Jsh[t][2];
        float* o = g_G2 + (size_t)(b * NJ + t) * 12;
        o[0] = g[0];  o[1] = g[1];  o[2]  = g[2];
        o[3] = g[3] - (g[0] * jx + g[1] * jy + g[2] * jz);
        o[4] = g[4];  o[5] = g[5];  o[6]  = g[6];
        o[7] = g[7] - (g[4] * jx + g[5] * jy + g[6] * jz);
        o[8] = g[8];  o[9] = g[9];  o[10] = g[10];
        o[11] = g[11] - (g[8] * jx + g[9] * jy + g[10] * jz);
        jtr[b * 72 + t * 3 + 0] = g[3]  + trans[b * 3 + 0];
        jtr[b * 72 + t * 3 + 1] = g[7]  + trans[b * 3 + 1];
        jtr[b * 72 + t * 3 + 2] = g[11] + trans[b * 3 + 2];
    }
}

// ---------------------------------------------------------------------------
// Kernel 2: tensor-core GEMM, bf16 3-mult hi/lo split, cp.async 2-stage.
// (R11 version -- measured 99.3us; reorder experiments were neutral.)
// ---------------------------------------------------------------------------
__global__ void __launch_bounds__(256, 2) k_mma() {
    extern __shared__ __align__(1024) char dsm[];
    uint32_t base = smem_u32(dsm);
    uint32_t sA[2] = { base, base + 16384 };
    uint32_t sB[2] = { base + 32768, base + 49152 };
    int tid = threadIdx.x;
    int w = tid >> 5, lane = tid & 31;
    int m0 = blockIdx.x * BN;
    int by = blockIdx.y;
    int wm = (w >> 1) * 32;
    int wn = (w & 1) * 64;

    float c[2][8][4];
#pragma unroll
    for (int mi = 0; mi < 2; mi++)
#pragma unroll
        for (int ni = 0; ni < 8; ni++)
#pragma unroll
            for (int e = 0; e < 4; e++) c[mi][ni][e] = 0.f;

    int row = tid >> 1, half = tid & 1;
    const __nv_bfloat16* gAh = g_Xhi + (size_t)(by * BM + row) * KP + half * 16;
    const __nv_bfloat16* gAl = g_Xlo + (size_t)(by * BM + row) * KP + half * 16;
    const __nv_bfloat16* gBh = g_Whi + (size_t)(m0 + row) * KP + half * 16;
    const __nv_bfloat16* gBl = g_Wlo + (size_t)(m0 + row) * KP + half * 16;
    uint32_t oA = row * 128 + half * 32;
    uint32_t d0 = SWZ(oA), d1 = SWZ(oA + 16), d2 = SWZ(oA + 64), d3 = SWZ(oA + 80);

#define ISSUE_CHUNK(kk, st) do { \
        CPASYNC16(sA[st] + d0, gAh + (kk)); \
        CPASYNC16(sA[st] + d1, gAh + (kk) + 8); \
        CPASYNC16(sA[st] + d2, gAl + (kk)); \
        CPASYNC16(sA[st] + d3, gAl + (kk) + 8); \
        CPASYNC16(sB[st] + d0, gBh + (kk)); \
        CPASYNC16(sB[st] + d1, gBh + (kk) + 8); \
        CPASYNC16(sB[st] + d2, gBl + (kk)); \
        CPASYNC16(sB[st] + d3, gBl + (kk) + 8); \
        CPCOMMIT(); \
    } while (0)

    uint32_t lA[2][2], lB[2][4];
#pragma unroll
    for (int ks = 0; ks < 2; ks++) {
#pragma unroll
        for (int mi = 0; mi < 2; mi++)
            lA[ks][mi] = (uint32_t)(wm + mi * 16 + (lane & 15)) * 128
                       + ks * 32 + (lane >> 4) * 16;
#pragma unroll
        for (int np = 0; np < 4; np++)
            lB[ks][np] = (uint32_t)(wn + np * 16 + ((lane >> 4) & 1) * 8 + (lane & 7)) * 128
                       + ks * 32 + ((lane >> 3) & 1) * 16;
    }

    ISSUE_CHUNK(0, 0);
    ISSUE_CHUNK(32, 1);
    CPWAIT(1);
    __syncthreads();

    for (int cc = 0; cc < NCH; cc++) {
        int cur = cc & 1;
#pragma unroll
        for (int ks = 0; ks < 2; ks++) {
            uint32_t Ah[2][4], Al[2][4];
#pragma unroll
            for (int mi = 0; mi < 2; mi++) {
                LDSM_X4(Ah[mi], sA[cur] + SWZ(lA[ks][mi]));
                LDSM_X4(Al[mi], sA[cur] + SWZ(lA[ks][mi] + 64));
            }
#pragma unroll
            for (int np = 0; np < 4; np++) {
                uint32_t rh[4], rl[4];
                LDSM_X4(rh, sB[cur] + SWZ(lB[ks][np]));
                LDSM_X4(rl, sB[cur] + SWZ(lB[ks][np] + 64));
#pragma unroll
                for (int mi = 0; mi < 2; mi++) {
                    MMA_BF16P(c[mi][2 * np],     Ah[mi], rh[0], rh[1]);
                    MMA_BF16P(c[mi][2 * np],     Ah[mi], rl[0], rl[1]);
                    MMA_BF16P(c[mi][2 * np],     Al[mi], rh[0], rh[1]);
                    MMA_BF16P(c[mi][2 * np + 1], Ah[mi], rh[2], rh[3]);
                    MMA_BF16P(c[mi][2 * np + 1], Ah[mi], rl[2], rl[3]);
                    MMA_BF16P(c[mi][2 * np + 1], Al[mi], rh[2], rh[3]);
                }
            }
        }
        __syncthreads();
        if (cc + 2 < NCH) {
            ISSUE_CHUNK((cc + 2) * 32, cur);
            CPWAIT(1);
        } else {
            CPWAIT(0);
        }
        if (cc + 1 < NCH) __syncthreads();
    }

    int gr = lane >> 2, tc = lane & 3;
#pragma unroll
    for (int mi = 0; mi < 2; mi++) {
        int b = by * BM + wm + mi * 16 + gr;
        float* rowp = g_vposed + (size_t)b * M_PAD;
#pragma unroll
        for (int ni = 0; ni < 8; ni++) {
            int m = m0 + wn + ni * 8 + tc * 2;
            if (m < M_TOT) {
                *(float2*)(rowp + m) = make_float2(c[mi][ni][0], c[mi][ni][1]);
                *(float2*)(rowp + (size_t)8 * M_PAD + m) = make_float2(c[mi][ni][2], c[mi][ni][3]);
            }
        }
    }
}

// ---------------------------------------------------------------------------
// Kernel 3: tensor-core skinning, 2 batches per MMA round, NB=16 per block
// (halves weight-fill traffic vs NB=8). At launch idx 3 for ncu capture.
// ---------------------------------------------------------------------------
__global__ void __launch_bounds__(256, 3) k_skinT(const float* __restrict__ trans,
                                                  float* __restrict__ out) {
    __shared__ __align__(1024) float sBuf[8192];    // 32 KB: Wh|Wl, reused as T
    __shared__ uint32_t sBpk[8 * 576];              // 18.4 KB packed B frags
    char* sWh = (char*)sBuf;
    char* sWl = (char*)sBuf + 16384;
    float* Tsm = sBuf;                              // [2][256][12] = 24 KB

    uint32_t swh = smem_u32(sWh), swl = smem_u32(sWl);
    int tid = threadIdx.x;
    int w = tid >> 5, lane = tid & 31;
    int b0 = blockIdx.x * NB;
    int vbase = blockIdx.y * 256;

    {
        const uint4* srch = (const uint4*)(g_WShi + (size_t)(vbase + tid) * 32);
        const uint4* srcl = (const uint4*)(g_WSlo + (size_t)(vbase + tid) * 32);
        uint32_t so = tid * 64;
#pragma unroll
        for (int q = 0; q < 4; q++) {
            sts128(swh + SWZ64(so + q * 16), srch[q]);
            sts128(swl + SWZ64(so + q * 16), srcl[q]);
        }
    }

    for (int i = 0; i < 18; i++) {
        int idx = tid + i * 256;
        int bl = idx & 31;
        int rest = idx >> 5;                 // 0..143
        int wI = rest % 3;
        int hl = (rest / 3) % 2;
        int nt = (rest / 6) % 3;
        int pi = rest / 18;                  // 0..7
        int n = nt * 8 + (bl >> 2);          // 0..23
        int bi = pi * 2 + (n >= 12 ? 1 : 0);
        int col = (n >= 12) ? n - 12 : n;
        int j0 = (wI == 0) ? (bl & 3) * 2
               : (wI == 1) ? (bl & 3) * 2 + 8
                           : 16 + (bl & 3) * 2;
        const float* g = g_G2 + ((size_t)(b0 + bi) * NJ + j0) * 12 + col;
        float v0 = g[0], v1 = g[12];
        __nv_bfloat16 h0 = __float2bfloat16(v0);
        __nv_bfloat16 h1 = __float2bfloat16(v1);
        if (hl) {
            h0 = __float2bfloat16(v0 - __bfloat162float(h0));
            h1 = __float2bfloat16(v1 - __bfloat162float(h1));
        }
        sBpk[idx] = ((uint32_t)__bfloat16_as_ushort(h1) << 16) | __bfloat16_as_ushort(h0);
    }
    __syncthreads();

    uint32_t Ah16[2][4], Al16[2][4], Ah8[2][2], Al8[2][2];
#pragma unroll
    for (int mt = 0; mt < 2; mt++) {
        uint32_t o16 = (uint32_t)(w * 32 + mt * 16 + (lane & 15)) * 64 + (lane >> 4) * 16;
        LDSM_X4(Ah16[mt], swh + SWZ64(o16));
        LDSM_X4(Al16[mt], swl + SWZ64(o16));
        uint32_t o8 = (uint32_t)(w * 32 + mt * 16 + (lane & 15)) * 64 + 32;
        LDSM_X2(Ah8[mt], swh + SWZ64(o8));
        LDSM_X2(Al8[mt], swl + SWZ64(o8));
    }
    __syncthreads();

    int gr = lane >> 2, tc = lane & 3;

    for (int pi = 0; pi < NB / 2; pi++) {
        float c[2][3][4];
#pragma unroll
        for (int mt = 0; mt < 2; mt++)
#pragma unroll
            for (int nt = 0; nt < 3; nt++)
#pragma unroll
                for (int e = 0; e < 4; e++) c[mt][nt][e] = 0.f;

        const uint32_t* bp = sBpk + pi * 576;
#pragma unroll
        for (int nt = 0; nt < 3; nt++) {
            uint32_t bh16[2] = { bp[(nt * 6 + 0) * 32 + lane], bp[(nt * 6 + 1) * 32 + lane] };
            uint32_t bh8     =   bp[(nt * 6 + 2) * 32 + lane];
            uint32_t bl16[2] = { bp[(nt * 6 + 3) * 32 + lane], bp[(nt * 6 + 4) * 32 + lane] };
            uint32_t bl8     =   bp[(nt * 6 + 5) * 32 + lane];
#pragma unroll
            for (int mt = 0; mt < 2; mt++) {
                MMA_BF16(c[mt][nt], Ah16[mt], bh16);
                MMA_BF16(c[mt][nt], Ah16[mt], bl16);
                MMA_BF16(c[mt][nt], Al16[mt], bh16);
                MMA_BF16_K8(c[mt][nt], Ah8[mt], bh8);
                MMA_BF16_K8(c[mt][nt], Ah8[mt], bl8);
                MMA_BF16_K8(c[mt][nt], Al8[mt], bh8);
            }
        }

#pragma unroll
        for (int mt = 0; mt < 2; mt++) {
            int v0 = w * 32 + mt * 16 + gr;
#pragma unroll
            for (int nt = 0; nt < 3; nt++) {
                int n0 = nt * 8 + tc * 2;          // even, 0..22
                int s = (n0 >= 12) ? 1 : 0;
                int col = n0 - s * 12;
                float* dst = &Tsm[(size_t)(s * 256 + v0) * 12 + col];
                *(float2*)dst = make_float2(c[mt][nt][0], c[mt][nt][1]);
                *(float2*)(dst + 8 * 12) = make_float2(c[mt][nt][2], c[mt][nt][3]);
            }
        }
        __syncthreads();

#pragma unroll
        for (int s = 0; s < 2; s++) {
            int b = b0 + pi * 2 + s;
            int v = vbase + tid;
            if (v < NV) {
                const float* Tq = &Tsm[(size_t)(s * 256 + tid) * 12];
                float4 T0 = *(const float4*)(Tq);
                float4 T1 = *(const float4*)(Tq + 4);
                float4 T2 = *(const float4*)(Tq + 8);
                const float* pp = g_vposed + (size_t)b * M_PAD + (size_t)v * 3;
                float px = pp[0], py = pp[1], pz = pp[2];
                float trx = trans[b * 3 + 0];
                float try_ = trans[b * 3 + 1];
                float trz = trans[b * 3 + 2];
                size_t o = (size_t)b * M_TOT + (size_t)v * 3;
                out[o + 0] = T0.x * px + T0.y * py + T0.z * pz + T0.w + trx;
                out[o + 1] = T1.x * px + T1.y * py + T1.z * pz + T1.w + try_;
                out[o + 2] = T2.x * px + T2.y * py + T2.z * pz + T2.w + trz;
            }
        }
        __syncthreads();
    }
}

// ---------------------------------------------------------------------------
extern "C" void kernel_launch(void* const* d_in, const int* in_sizes, int n_in,
                              void* d_out, int out_size) {
    const float* pose  = (const float*)d_in[0];  // [1024,72]
    const float* betas = (const float*)d_in[1];  // [1024,10]
    const float* trans = (const float*)d_in[2];  // [1024,3]
    const float* vt    = (const float*)d_in[3];  // [6890,3]
    const float* sd    = (const float*)d_in[4];  // [6890,3,10]
    const float* pd    = (const float*)d_in[5];  // [6890,3,207]
    const float* jreg  = (const float*)d_in[6];  // [24,6890]
    const float* wts   = (const float*)d_in[7];  // [6890,24]
    float* out = (float*)d_out;
    float* jtr = out + (size_t)BATCH * M_TOT;

    cudaFuncSetAttribute(k_mma, cudaFuncAttributeMaxDynamicSharedMemorySize, SMEM_MMA);

    // 4 launches; k_skinT at index 3 (ncu captures idx 3)
    k_prep<<<WBLK2 + WSBLK + NJ, 256>>>(pd, sd, vt, wts, jreg);            // 0
    k_pose<<<BATCH, 32>>>(pose, betas, trans, jtr);                        // 1
    k_mma<<<dim3(M_WPAD / BN, BATCH / BM), 256, SMEM_MMA>>>();             // 2
    k_skinT<<<dim3(BATCH / NB, NVP / 256), 256>>>(trans, out);             // 3
}

// round 14
// speedup vs baseline: 1.0837x; 1.0837x over previous
#include <cuda_runtime.h>
#include <cuda_bf16.h>
#include <math.h>
#include <stdint.h>

#define BATCH 1024
#define NJ 24
#define NV 6890
#define NVP 6912             // 27*256 padded verts
#define M_TOT 20670          // NV*3
#define M_PAD 20672          // row stride for v_posed
#define K_TOT 224
#define KP 256               // padded K stride for bf16 operand storage
#define M_WPAD 20736         // 162*128, padded rows of W

#define BM 128               // batch tile (main gemm)
#define BN 128               // m tile (main gemm)
#define NCH 7                // 7 * 32 = 224 K-chunks
#define SMEM_MMA 65536       // 2 stages x (16KB A + 16KB B)

#define NB 16                // batches per skin block
#define NSL 27               // vert slices for jpart
#define WBLK2 2592           // prep blocks for W conv (M_WPAD*32/256)
#define WSBLK 108            // prep blocks for skin-weight conv (NVP*4/256)

__constant__ int c_par[NJ] = {-1,0,0,0,1,2,3,4,5,6,7,8,9,9,9,12,13,14,16,17,18,19,20,21};

// Scratch (device globals -- no runtime allocation allowed)
__device__ float g_G2[BATCH * NJ * 12];
__device__ float g_Jpart[NJ * NSL * 33];
__device__ float g_Jv[NJ * 3];
__device__ float g_Js[NJ * 30];
__device__ float g_vposed[(size_t)BATCH * M_PAD + 1024];
__device__ __nv_bfloat16 g_Xhi[BATCH * KP];
__device__ __nv_bfloat16 g_Xlo[BATCH * KP];
__device__ __nv_bfloat16 g_Whi[(size_t)M_WPAD * KP];
__device__ __nv_bfloat16 g_Wlo[(size_t)M_WPAD * KP];
__device__ __nv_bfloat16 g_WShi[NVP * 32];
__device__ __nv_bfloat16 g_WSlo[NVP * 32];

// ---------------------------------------------------------------------------
// helpers
// ---------------------------------------------------------------------------
__device__ __forceinline__ uint32_t smem_u32(const void* p) {
    uint32_t a;
    asm("{ .reg .u64 t; cvta.to.shared.u64 t, %1; cvt.u32.u64 %0, t; }" : "=r"(a) : "l"(p));
    return a;
}
__device__ __forceinline__ void sts128(uint32_t a, uint4 v) {
    asm volatile("st.shared.v4.b32 [%0], {%1,%2,%3,%4};"
                 :: "r"(a), "r"(v.x), "r"(v.y), "r"(v.z), "r"(v.w) : "memory");
}
#define SWZ(o) ((o) ^ (((o) >> 3) & 0x70))
#define SWZ64(o) ((o) ^ (((o) >> 3) & 0x30))

#define CPASYNC16(sm, gp) \
    asm volatile("cp.async.cg.shared.global [%0], [%1], 16;" :: "r"(sm), "l"(gp) : "memory")
#define CPCOMMIT() asm volatile("cp.async.commit_group;" ::: "memory")
#define CPWAIT(n)  asm volatile("cp.async.wait_group %0;" :: "n"(n) : "memory")

#define LDSM_X4(R, ADDR) \
    asm volatile("ldmatrix.sync.aligned.m8n8.x4.shared.b16 {%0,%1,%2,%3}, [%4];" \
        : "=r"((R)[0]), "=r"((R)[1]), "=r"((R)[2]), "=r"((R)[3]) : "r"(ADDR))

#define LDSM_X2(R, ADDR) \
    asm volatile("ldmatrix.sync.aligned.m8n8.x2.shared.b16 {%0,%1}, [%2];" \
        : "=r"((R)[0]), "=r"((R)[1]) : "r"(ADDR))

#define MMA_BF16(C, A, B) \
    asm volatile("mma.sync.aligned.m16n8k16.row.col.f32.bf16.bf16.f32 " \
        "{%0,%1,%2,%3},{%4,%5,%6,%7},{%8,%9},{%0,%1,%2,%3};" \
        : "+f"((C)[0]), "+f"((C)[1]), "+f"((C)[2]), "+f"((C)[3]) \
        : "r"((A)[0]), "r"((A)[1]), "r"((A)[2]), "r"((A)[3]), "r"((B)[0]), "r"((B)[1]))

#define MMA_BF16P(C, A, b0, b1) \
    asm volatile("mma.sync.aligned.m16n8k16.row.col.f32.bf16.bf16.f32 " \
        "{%0,%1,%2,%3},{%4,%5,%6,%7},{%8,%9},{%0,%1,%2,%3};" \
        : "+f"((C)[0]), "+f"((C)[1]), "+f"((C)[2]), "+f"((C)[3]) \
        : "r"((A)[0]), "r"((A)[1]), "r"((A)[2]), "r"((A)[3]), "r"(b0), "r"(b1))

#define MMA_BF16_K8(C, A, B) \
    asm volatile("mma.sync.aligned.m16n8k8.row.col.f32.bf16.bf16.f32 " \
        "{%0,%1,%2,%3},{%4,%5},{%6},{%0,%1,%2,%3};" \
        : "+f"((C)[0]), "+f"((C)[1]), "+f"((C)[2]), "+f"((C)[3]) \
        : "r"((A)[0]), "r"((A)[1]), "r"(B))

// ---------------------------------------------------------------------------
// bf16 hi/lo pack
// ---------------------------------------------------------------------------
__device__ __forceinline__ void pack8(const float* v, uint4* hi4, uint4* lo4) {
    uint32_t hi[4], lo[4];
#pragma unroll
    for (int i = 0; i < 4; i++) {
        __nv_bfloat16 h0 = __float2bfloat16(v[2 * i]);
        __nv_bfloat16 h1 = __float2bfloat16(v[2 * i + 1]);
        __nv_bfloat16 l0 = __float2bfloat16(v[2 * i] - __bfloat162float(h0));
        __nv_bfloat16 l1 = __float2bfloat16(v[2 * i + 1] - __bfloat162float(h1));
        hi[i] = ((uint32_t)__bfloat16_as_ushort(h1) << 16) | __bfloat16_as_ushort(h0);
        lo[i] = ((uint32_t)__bfloat16_as_ushort(l1) << 16) | __bfloat16_as_ushort(l0);
    }
    *hi4 = make_uint4(hi[0], hi[1], hi[2], hi[3]);
    *lo4 = make_uint4(lo[0], lo[1], lo[2], lo[3]);
}

// ---------------------------------------------------------------------------
// Kernel 0 (prep): W conv + skin-weight conv + SLICED jpart partials
// (shapedirs staged in smem once per slice -- the fast version).
// ---------------------------------------------------------------------------
__global__ void __launch_bounds__(256) k_prep(const float* __restrict__ pd,
                                              const float* __restrict__ sd,
                                              const float* __restrict__ vt,
                                              const float* __restrict__ wts,
                                              const float* __restrict__ Jreg) {
    int bid = blockIdx.x;
    int t = threadIdx.x;
    if (bid < WBLK2) {
        int idx = bid * 256 + t;          // over M_WPAD*32
        int m = idx >> 5;
        int k0 = (idx & 31) * 8;
        float v[8];
#pragma unroll
        for (int i = 0; i < 8; i++) {
            int k = k0 + i;
            float x = 0.f;
            if (m < M_TOT) {
                if (k < 207)       x = pd[(size_t)m * 207 + k];
                else if (k < 217)  x = sd[(size_t)m * 10 + (k - 207)];
                else if (k == 217) x = vt[m];
            }
            v[i] = x;
        }
        uint4 hi4, lo4;
        pack8(v, &hi4, &lo4);
        size_t off = (size_t)idx * 8;
        *(uint4*)(g_Whi + off) = hi4;
        *(uint4*)(g_Wlo + off) = lo4;
    } else if (bid < WBLK2 + WSBLK) {
        int idx = (bid - WBLK2) * 256 + t;  // over NVP*4
        int vv = idx >> 2;
        int k0 = (idx & 3) * 8;
        float v[8];
#pragma unroll
        for (int i = 0; i < 8; i++) {
            int k = k0 + i;
            v[i] = (vv < NV && k < 24) ? wts[vv * 24 + k] : 0.f;
        }
        uint4 hi4, lo4;
        pack8(v, &hi4, &lo4);
        size_t off = (size_t)idx * 8;
        *(uint4*)(g_WShi + off) = hi4;
        *(uint4*)(g_WSlo + off) = lo4;
    } else {
        // sliced jpart: stage vt+sd for 256 verts once, warps do 3 joints each
        __shared__ float vals[256][34];
        int sl = bid - WBLK2 - WSBLK;
        int vbase = sl * 256;
        int v = vbase + t;
        if (v < NV) {
            vals[t][0] = vt[v * 3 + 0];
            vals[t][1] = vt[v * 3 + 1];
            vals[t][2] = vt[v * 3 + 2];
            const float* sp = sd + (size_t)v * 30;
#pragma unroll
            for (int e = 0; e < 30; e++) vals[t][3 + e] = sp[e];
        } else {
#pragma unroll
            for (int e = 0; e < 33; e++) vals[t][e] = 0.f;
        }
        __syncthreads();

        int w = t >> 5, lane = t & 31;
        for (int jj = 0; jj < 3; jj++) {
            int j = w * 3 + jj;
            float acc[33];
#pragma unroll
            for (int e = 0; e < 33; e++) acc[e] = 0.f;
            for (int vl = lane; vl < 256; vl += 32) {
                int vg = vbase + vl;
                float r = (vg < NV) ? Jreg[j * NV + vg] : 0.f;
#pragma unroll
                for (int e = 0; e < 33; e++) acc[e] += r * vals[vl][e];
            }
#pragma unroll
            for (int e = 0; e < 33; e++) {
#pragma unroll
                for (int o = 16; o > 0; o >>= 1)
                    acc[e] += __shfl_xor_sync(0xffffffffu, acc[e], o);
            }
            if (lane == 0) {
#pragma unroll
                for (int e = 0; e < 33; e++)
                    g_Jpart[(j * NSL + sl) * 33 + e] = acc[e];
            }
        }
    }
}

__global__ void k_jreduce() {
    int t = threadIdx.x;
    if (t < NJ * 33) {
        int j = t / 33, e = t % 33;
        float r = 0.f;
#pragma unroll
        for (int s = 0; s < NSL; s++) r += g_Jpart[(j * NSL + s) * 33 + e];
        if (e < 3) g_Jv[j * 3 + e] = r;
        else       g_Js[j * 30 + (e - 3)] = r;
    }
}

// ---------------------------------------------------------------------------
// Kernel: Rodrigues + kinematic chain + G2 + jtr; writes X as bf16 hi/lo.
// ---------------------------------------------------------------------------
__device__ __forceinline__ void wr_xsplit(int idx, float v) {
    __nv_bfloat16 h = __float2bfloat16(v);
    g_Xhi[idx] = h;
    g_Xlo[idx] = __float2bfloat16(v - __bfloat162float(h));
}

__global__ void k_pose(const float* __restrict__ pose,
                       const float* __restrict__ betas,
                       const float* __restrict__ trans,
                       float* __restrict__ jtr) {
    int b = blockIdx.x, t = threadIdx.x;
    __shared__ float Rsh[NJ][9];
    __shared__ float Jsh[NJ][3];
    __shared__ float G[NJ][16];

    if (t < NJ) {
        float ax = pose[b * 72 + t * 3 + 0];
        float ay = pose[b * 72 + t * 3 + 1];
        float az = pose[b * 72 + t * 3 + 2];
        float th = sqrtf(ax * ax + ay * ay + az * az + 1e-8f);
        float inv = 1.f / th;
        float kx = ax * inv, ky = ay * inv, kz = az * inv;
        float ct = cosf(th), st = sinf(th);
        float K[9] = {0.f, -kz, ky, kz, 0.f, -kx, -ky, kx, 0.f};
        float Rm[9];
#pragma unroll
        for (int r = 0; r < 3; r++) {
#pragma unroll
            for (int c = 0; c < 3; c++) {
                float k2 = K[r * 3 + 0] * K[0 + c] + K[r * 3 + 1] * K[3 + c] + K[r * 3 + 2] * K[6 + c];
                Rm[r * 3 + c] = ((r == c) ? 1.f : 0.f) + st * K[r * 3 + c] + (1.f - ct) * k2;
            }
        }
#pragma unroll
        for (int e = 0; e < 9; e++) Rsh[t][e] = Rm[e];
        if (t >= 1) {
#pragma unroll
            for (int e = 0; e < 9; e++)
                wr_xsplit(b * KP + (t - 1) * 9 + e,
                          Rm[e] - ((e == 0 || e == 4 || e == 8) ? 1.f : 0.f));
        }
#pragma unroll
        for (int c = 0; c < 3; c++) {
            float v = g_Jv[t * 3 + c];
#pragma unroll
            for (int s = 0; s < 10; s++)
                v += g_Js[t * 30 + c * 10 + s] * betas[b * 10 + s];
            Jsh[t][c] = v;
        }
    }
    if (t < 17) {
        float v = (t < 10) ? betas[b * 10 + t] : ((t == 10) ? 1.f : 0.f);
        wr_xsplit(b * KP + 207 + t, v);
    }
    {
        int k = 224 + t;                 // zero tail 224..255
        g_Xhi[b * KP + k] = __float2bfloat16(0.f);
        g_Xlo[b * KP + k] = __float2bfloat16(0.f);
    }
    __syncwarp();

    if (t < 16) {
        int r = t >> 2, c = t & 3;
        G[0][t] = (r < 3) ? ((c < 3) ? Rsh[0][r * 3 + c] : Jsh[0][r])
                          : ((c == 3) ? 1.f : 0.f);
    }
    __syncwarp();

    for (int i = 1; i < NJ; i++) {
        int p = c_par[i];
        float v = 0.f;
        if (t < 16) {
            int r = t >> 2, c = t & 3;
            float l0, l1, l2, l3;
            if (c < 3) {
                l0 = Rsh[i][c]; l1 = Rsh[i][3 + c]; l2 = Rsh[i][6 + c]; l3 = 0.f;
            } else {
                l0 = Jsh[i][0] - Jsh[p][0];
                l1 = Jsh[i][1] - Jsh[p][1];
                l2 = Jsh[i][2] - Jsh[p][2];
                l3 = 1.f;
            }
            v = G[p][r * 4 + 0] * l0 + G[p][r * 4 + 1] * l1 +
                G[p][r * 4 + 2] * l2 + G[p][r * 4 + 3] * l3;
        }
        __syncwarp();
        if (t < 16) G[i][t] = v;
        __syncwarp();
    }

    if (t < NJ) {
        const float* g = G[t];
        float jx = Jsh[t][0], jy = Jsh[t][1], jz = Jsh[t][2];
        float* o = g_G2 + (size_t)(b * NJ + t) * 12;
        o[0] = g[0];  o[1] = g[1];  o[2]  = g[2];
        o[3] = g[3] - (g[0] * jx + g[1] * jy + g[2] * jz);
        o[4] = g[4];  o[5] = g[5];  o[6]  = g[6];
        o[7] = g[7] - (g[4] * jx + g[5] * jy + g[6] * jz);
        o[8] = g[8];  o[9] = g[9];  o[10] = g[10];
        o[11] = g[11] - (g[8] * jx + g[9] * jy + g[10] * jz);
        jtr[b * 72 + t * 3 + 0] = g[3]  + trans[b * 3 + 0];
        jtr[b * 72 + t * 3 + 1] = g[7]  + trans[b * 3 + 1];
        jtr[b * 72 + t * 3 + 2] = g[11] + trans[b * 3 + 2];
    }
}

// ---------------------------------------------------------------------------
// Kernel: tensor-core GEMM, bf16 3-mult hi/lo split, cp.async 2-stage.
// ---------------------------------------------------------------------------
__global__ void __launch_bounds__(256, 2) k_mma() {
    extern __shared__ __align__(1024) char dsm[];
    uint32_t base = smem_u32(dsm);
    uint32_t sA[2] = { base, base + 16384 };
    uint32_t sB[2] = { base + 32768, base + 49152 };
    int tid = threadIdx.x;
    int w = tid >> 5, lane = tid & 31;
    int m0 = blockIdx.x * BN;
    int by = blockIdx.y;
    int wm = (w >> 1) * 32;
    int wn = (w & 1) * 64;

    float c[2][8][4];
#pragma unroll
    for (int mi = 0; mi < 2; mi++)
#pragma unroll
        for (int ni = 0; ni < 8; ni++)
#pragma unroll
            for (int e = 0; e < 4; e++) c[mi][ni][e] = 0.f;

    int row = tid >> 1, half = tid & 1;
    const __nv_bfloat16* gAh = g_Xhi + (size_t)(by * BM + row) * KP + half * 16;
    const __nv_bfloat16* gAl = g_Xlo + (size_t)(by * BM + row) * KP + half * 16;
    const __nv_bfloat16* gBh = g_Whi + (size_t)(m0 + row) * KP + half * 16;
    const __nv_bfloat16* gBl = g_Wlo + (size_t)(m0 + row) * KP + half * 16;
    uint32_t oA = row * 128 + half * 32;
    uint32_t d0 = SWZ(oA), d1 = SWZ(oA + 16), d2 = SWZ(oA + 64), d3 = SWZ(oA + 80);

#define ISSUE_CHUNK(kk, st) do { \
        CPASYNC16(sA[st] + d0, gAh + (kk)); \
        CPASYNC16(sA[st] + d1, gAh + (kk) + 8); \
        CPASYNC16(sA[st] + d2, gAl + (kk)); \
        CPASYNC16(sA[st] + d3, gAl + (kk) + 8); \
        CPASYNC16(sB[st] + d0, gBh + (kk)); \
        CPASYNC16(sB[st] + d1, gBh + (kk) + 8); \
        CPASYNC16(sB[st] + d2, gBl + (kk)); \
        CPASYNC16(sB[st] + d3, gBl + (kk) + 8); \
        CPCOMMIT(); \
    } while (0)

    uint32_t lA[2][2], lB[2][4];
#pragma unroll
    for (int ks = 0; ks < 2; ks++) {
#pragma unroll
        for (int mi = 0; mi < 2; mi++)
            lA[ks][mi] = (uint32_t)(wm + mi * 16 + (lane & 15)) * 128
                       + ks * 32 + (lane >> 4) * 16;
#pragma unroll
        for (int np = 0; np < 4; np++)
            lB[ks][np] = (uint32_t)(wn + np * 16 + ((lane >> 4) & 1) * 8 + (lane & 7)) * 128
                       + ks * 32 + ((lane >> 3) & 1) * 16;
    }

    ISSUE_CHUNK(0, 0);
    ISSUE_CHUNK(32, 1);
    CPWAIT(1);
    __syncthreads();

    for (int cc = 0; cc < NCH; cc++) {
        int cur = cc & 1;
#pragma unroll
        for (int ks = 0; ks < 2; ks++) {
            uint32_t Ah[2][4], Al[2][4];
#pragma unroll
            for (int mi = 0; mi < 2; mi++) {
                LDSM_X4(Ah[mi], sA[cur] + SWZ(lA[ks][mi]));
                LDSM_X4(Al[mi], sA[cur] + SWZ(lA[ks][mi] + 64));
            }
#pragma unroll
            for (int np = 0; np < 4; np++) {
                uint32_t rh[4], rl[4];
                LDSM_X4(rh, sB[cur] + SWZ(lB[ks][np]));
                LDSM_X4(rl, sB[cur] + SWZ(lB[ks][np] + 64));
#pragma unroll
                for (int mi = 0; mi < 2; mi++) {
                    MMA_BF16P(c[mi][2 * np],     Ah[mi], rh[0], rh[1]);
                    MMA_BF16P(c[mi][2 * np],     Ah[mi], rl[0], rl[1]);
                    MMA_BF16P(c[mi][2 * np],     Al[mi], rh[0], rh[1]);
                    MMA_BF16P(c[mi][2 * np + 1], Ah[mi], rh[2], rh[3]);
                    MMA_BF16P(c[mi][2 * np + 1], Ah[mi], rl[2], rl[3]);
                    MMA_BF16P(c[mi][2 * np + 1], Al[mi], rh[2], rh[3]);
                }
            }
        }
        __syncthreads();
        if (cc + 2 < NCH) {
            ISSUE_CHUNK((cc + 2) * 32, cur);
            CPWAIT(1);
        } else {
            CPWAIT(0);
        }
        if (cc + 1 < NCH) __syncthreads();
    }

    int gr = lane >> 2, tc = lane & 3;
#pragma unroll
    for (int mi = 0; mi < 2; mi++) {
        int b = by * BM + wm + mi * 16 + gr;
        float* rowp = g_vposed + (size_t)b * M_PAD;
#pragma unroll
        for (int ni = 0; ni < 8; ni++) {
            int m = m0 + wn + ni * 8 + tc * 2;
            if (m < M_TOT) {
                *(float2*)(rowp + m) = make_float2(c[mi][ni][0], c[mi][ni][1]);
                *(float2*)(rowp + (size_t)8 * M_PAD + m) = make_float2(c[mi][ni][2], c[mi][ni][3]);
            }
        }
    }
}

// ---------------------------------------------------------------------------
// Kernel: tensor-core skinning with SHUFFLE epilogue (no T smem round-trip,
// no per-pair syncthreads). NB=16 batches per block.
// ---------------------------------------------------------------------------
__global__ void __launch_bounds__(256, 3) k_skinT(const float* __restrict__ trans,
                                                  float* __restrict__ out) {
    __shared__ __align__(1024) char sWh[256 * 64];   // 16 KB weights hi
    __shared__ __align__(1024) char sWl[256 * 64];   // 16 KB weights lo
    __shared__ uint32_t sBpk[8 * 576];               // 18.4 KB packed B frags

    uint32_t swh = smem_u32(sWh), swl = smem_u32(sWl);
    int tid = threadIdx.x;
    int w = tid >> 5, lane = tid & 31;
    int b0 = blockIdx.x * NB;
    int vbase = blockIdx.y * 256;

    {
        const uint4* srch = (const uint4*)(g_WShi + (size_t)(vbase + tid) * 32);
        const uint4* srcl = (const uint4*)(g_WSlo + (size_t)(vbase + tid) * 32);
        uint32_t so = tid * 64;
#pragma unroll
        for (int q = 0; q < 4; q++) {
            sts128(swh + SWZ64(so + q * 16), srch[q]);
            sts128(swl + SWZ64(so + q * 16), srcl[q]);
        }
    }

    for (int i = 0; i < 18; i++) {
        int idx = tid + i * 256;
        int bl = idx & 31;
        int rest = idx >> 5;                 // 0..143
        int wI = rest % 3;
        int hl = (rest / 3) % 2;
        int nt = (rest / 6) % 3;
        int pi = rest / 18;                  // 0..7
        int n = nt * 8 + (bl >> 2);          // 0..23
        int bi = pi * 2 + (n >= 12 ? 1 : 0);
        int col = (n >= 12) ? n - 12 : n;
        int j0 = (wI == 0) ? (bl & 3) * 2
               : (wI == 1) ? (bl & 3) * 2 + 8
                           : 16 + (bl & 3) * 2;
        const float* g = g_G2 + ((size_t)(b0 + bi) * NJ + j0) * 12 + col;
        float v0 = g[0], v1 = g[12];
        __nv_bfloat16 h0 = __float2bfloat16(v0);
        __nv_bfloat16 h1 = __float2bfloat16(v1);
        if (hl) {
            h0 = __float2bfloat16(v0 - __bfloat162float(h0));
            h1 = __float2bfloat16(v1 - __bfloat162float(h1));
        }
        sBpk[idx] = ((uint32_t)__bfloat16_as_ushort(h1) << 16) | __bfloat16_as_ushort(h0);
    }
    __syncthreads();

    uint32_t Ah16[2][4], Al16[2][4], Ah8[2][2], Al8[2][2];
#pragma unroll
    for (int mt = 0; mt < 2; mt++) {
        uint32_t o16 = (uint32_t)(w * 32 + mt * 16 + (lane & 15)) * 64 + (lane >> 4) * 16;
        LDSM_X4(Ah16[mt], swh + SWZ64(o16));
        LDSM_X4(Al16[mt], swl + SWZ64(o16));
        uint32_t o8 = (uint32_t)(w * 32 + mt * 16 + (lane & 15)) * 64 + 32;
        LDSM_X2(Ah8[mt], swh + SWZ64(o8));
        LDSM_X2(Al8[mt], swl + SWZ64(o8));
    }
    // no further syncthreads needed: sBpk is read-only from here, frags in regs

    int gr = lane >> 2, tc = lane & 3;

    for (int pi = 0; pi < NB / 2; pi++) {
        float c[2][3][4];
#pragma unroll
        for (int mt = 0; mt < 2; mt++)
#pragma unroll
            for (int nt = 0; nt < 3; nt++)
#pragma unroll
                for (int e = 0; e < 4; e++) c[mt][nt][e] = 0.f;

        const uint32_t* bp = sBpk + pi * 576;
#pragma unroll
        for (int nt = 0; nt < 3; nt++) {
            uint32_t bh16[2] = { bp[(nt * 6 + 0) * 32 + lane], bp[(nt * 6 + 1) * 32 + lane] };
            uint32_t bh8     =   bp[(nt * 6 + 2) * 32 + lane];
            uint32_t bl16[2] = { bp[(nt * 6 + 3) * 32 + lane], bp[(nt * 6 + 4) * 32 + lane] };
            uint32_t bl8     =   bp[(nt * 6 + 5) * 32 + lane];
#pragma unroll
            for (int mt = 0; mt < 2; mt++) {
                MMA_BF16(c[mt][nt], Ah16[mt], bh16);
                MMA_BF16(c[mt][nt], Ah16[mt], bl16);
                MMA_BF16(c[mt][nt], Al16[mt], bh16);
                MMA_BF16_K8(c[mt][nt], Ah8[mt], bh8);
                MMA_BF16_K8(c[mt][nt], Ah8[mt], bl8);
                MMA_BF16_K8(c[mt][nt], Al8[mt], bh8);
            }
        }

        // shuffle epilogue: apply T * [p;1] + trans directly from fragments
#pragma unroll
        for (int s = 0; s < 2; s++) {
            int b = b0 + pi * 2 + s;
            // own vertex p (thread tid <-> vert vbase + w*32 + lane)
            const float* pown = g_vposed + (size_t)b * M_PAD
                              + (size_t)(vbase + w * 32 + lane) * 3;
            float pox = pown[0], poy = pown[1], poz = pown[2];
            float tr = (tc < 3) ? trans[b * 3 + tc] : 0.f;
#pragma unroll
            for (int mt = 0; mt < 2; mt++) {
#pragma unroll
                for (int h = 0; h < 2; h++) {
                    int L = mt * 16 + h * 8 + gr;   // lane owning this vertex's p
                    float px = __shfl_sync(0xffffffffu, pox, L);
                    float py = __shfl_sync(0xffffffffu, poy, L);
                    float pz = __shfl_sync(0xffffffffu, poz, L);
                    float mul[4] = { px, py, pz, 1.f };
                    float pr0 = 0.f, pr1 = 0.f, pr2 = 0.f;
                    float e0, e1;
                    if (s == 0) {
                        // nt0: cols tc*2, tc*2+1 -> row tc/2
                        e0 = c[mt][0][h * 2 + 0] * mul[(tc * 2) & 3]
                           + c[mt][0][h * 2 + 1] * mul[(tc * 2 + 1) & 3];
                        if (tc < 2) pr0 = e0; else pr1 = e0;
                        if (tc < 2) {
                            // nt1: cols 8+tc*2 -> row 2
                            pr2 = c[mt][1][h * 2 + 0] * mul[(8 + tc * 2) & 3]
                                + c[mt][1][h * 2 + 1] * mul[(9 + tc * 2) & 3];
                        }
                    } else {
                        if (tc >= 2) {
                            // nt1: cols tc*2-4 -> row 0
                            pr0 = c[mt][1][h * 2 + 0] * mul[(tc * 2 - 4) & 3]
                                + c[mt][1][h * 2 + 1] * mul[(tc * 2 - 3) & 3];
                        }
                        // nt2: cols 4+tc*2 -> row (4+tc*2)/4
                        e1 = c[mt][2][h * 2 + 0] * mul[(4 + tc * 2) & 3]
                           + c[mt][2][h * 2 + 1] * mul[(5 + tc * 2) & 3];
                        if (tc < 2) pr1 += e1; else pr2 += e1;
                    }
                    // butterfly across the quad (tc = lane&3)
                    pr0 += __shfl_xor_sync(0xffffffffu, pr0, 1);
                    pr0 += __shfl_xor_sync(0xffffffffu, pr0, 2);
                    pr1 += __shfl_xor_sync(0xffffffffu, pr1, 1);
                    pr1 += __shfl_xor_sync(0xffffffffu, pr1, 2);
                    pr2 += __shfl_xor_sync(0xffffffffu, pr2, 1);
                    pr2 += __shfl_xor_sync(0xffffffffu, pr2, 2);
                    int v = vbase + w * 32 + L;
                    if (tc < 3 && v < NV) {
                        float r = (tc == 0) ? pr0 : (tc == 1) ? pr1 : pr2;
                        out[(size_t)b * M_TOT + (size_t)v * 3 + tc] = r + tr;
                    }
                }
            }
        }
    }
}

// ---------------------------------------------------------------------------
extern "C" void kernel_launch(void* const* d_in, const int* in_sizes, int n_in,
                              void* d_out, int out_size) {
    const float* pose  = (const float*)d_in[0];  // [1024,72]
    const float* betas = (const float*)d_in[1];  // [1024,10]
    const float* trans = (const float*)d_in[2];  // [1024,3]
    const float* vt    = (const float*)d_in[3];  // [6890,3]
    const float* sd    = (const float*)d_in[4];  // [6890,3,10]
    const float* pd    = (const float*)d_in[5];  // [6890,3,207]
    const float* jreg  = (const float*)d_in[6];  // [24,6890]
    const float* wts   = (const float*)d_in[7];  // [6890,24]
    float* out = (float*)d_out;
    float* jtr = out + (size_t)BATCH * M_TOT;

    cudaFuncSetAttribute(k_mma, cudaFuncAttributeMaxDynamicSharedMemorySize, SMEM_MMA);

    k_prep<<<WBLK2 + WSBLK + NSL, 256>>>(pd, sd, vt, wts, jreg);           // 0
    k_jreduce<<<1, 792>>>();                                               // 1
    k_pose<<<BATCH, 32>>>(pose, betas, trans, jtr);                        // 2
    k_mma<<<dim3(M_WPAD / BN, BATCH / BM), 256, SMEM_MMA>>>();             // 3
    k_skinT<<<dim3(BATCH / NB, NVP / 256), 256>>>(trans, out);             // 4
}

// round 15
// speedup vs baseline: 1.1669x; 1.0768x over previous
#include <cuda_runtime.h>
#include <cuda_bf16.h>
#include <math.h>
#include <stdint.h>

#define BATCH 1024
#define NJ 24
#define NV 6890
#define NVP 6912             // 27*256 padded verts
#define M_TOT 20670          // NV*3
#define M_PAD 20672          // row stride for v_posed
#define K_TOT 224
#define KP 256               // padded K stride for bf16 operand storage
#define M_WPAD 20736         // 162*128, padded rows of W

#define BM 128               // batch tile (main gemm)
#define BN 128               // m tile (main gemm)
#define NCH 7                // 7 * 32 = 224 K-chunks
#define SMEM_MMA 65536       // 2 stages x (16KB A + 16KB B)

#define NB 16                // batches per skin block
#define NSL 27               // vert slices for jpart
#define WBLK2 2592           // prep blocks for W conv (M_WPAD*32/256)
#define WSBLK 108            // prep blocks for skin-weight conv (NVP*4/256)

__constant__ int c_par[NJ] = {-1,0,0,0,1,2,3,4,5,6,7,8,9,9,9,12,13,14,16,17,18,19,20,21};

// Scratch (device globals -- no runtime allocation allowed)
__device__ float g_G2[BATCH * NJ * 12];
__device__ float g_Jpart[NJ * NSL * 33];
__device__ float g_Jv[NJ * 3];
__device__ float g_Js[NJ * 30];
__device__ float g_vposed[(size_t)BATCH * M_PAD + 1024];
__device__ __nv_bfloat16 g_Xhi[BATCH * KP];
__device__ __nv_bfloat16 g_Xlo[BATCH * KP];
__device__ __nv_bfloat16 g_Whi[(size_t)M_WPAD * KP];
__device__ __nv_bfloat16 g_Wlo[(size_t)M_WPAD * KP];
__device__ __nv_bfloat16 g_WShi[NVP * 32];
__device__ __nv_bfloat16 g_WSlo[NVP * 32];

// ---------------------------------------------------------------------------
// helpers
// ---------------------------------------------------------------------------
__device__ __forceinline__ uint32_t smem_u32(const void* p) {
    uint32_t a;
    asm("{ .reg .u64 t; cvta.to.shared.u64 t, %1; cvt.u32.u64 %0, t; }" : "=r"(a) : "l"(p));
    return a;
}
__device__ __forceinline__ void sts128(uint32_t a, uint4 v) {
    asm volatile("st.shared.v4.b32 [%0], {%1,%2,%3,%4};"
                 :: "r"(a), "r"(v.x), "r"(v.y), "r"(v.z), "r"(v.w) : "memory");
}
#define SWZ(o) ((o) ^ (((o) >> 3) & 0x70))
#define SWZ64(o) ((o) ^ (((o) >> 3) & 0x30))

#define CPASYNC16(sm, gp) \
    asm volatile("cp.async.cg.shared.global [%0], [%1], 16;" :: "r"(sm), "l"(gp) : "memory")
#define CPCOMMIT() asm volatile("cp.async.commit_group;" ::: "memory")
#define CPWAIT(n)  asm volatile("cp.async.wait_group %0;" :: "n"(n) : "memory")

#define LDSM_X4(R, ADDR) \
    asm volatile("ldmatrix.sync.aligned.m8n8.x4.shared.b16 {%0,%1,%2,%3}, [%4];" \
        : "=r"((R)[0]), "=r"((R)[1]), "=r"((R)[2]), "=r"((R)[3]) : "r"(ADDR))

#define LDSM_X2(R, ADDR) \
    asm volatile("ldmatrix.sync.aligned.m8n8.x2.shared.b16 {%0,%1}, [%2];" \
        : "=r"((R)[0]), "=r"((R)[1]) : "r"(ADDR))

#define MMA_BF16(C, A, B) \
    asm volatile("mma.sync.aligned.m16n8k16.row.col.f32.bf16.bf16.f32 " \
        "{%0,%1,%2,%3},{%4,%5,%6,%7},{%8,%9},{%0,%1,%2,%3};" \
        : "+f"((C)[0]), "+f"((C)[1]), "+f"((C)[2]), "+f"((C)[3]) \
        : "r"((A)[0]), "r"((A)[1]), "r"((A)[2]), "r"((A)[3]), "r"((B)[0]), "r"((B)[1]))

#define MMA_BF16P(C, A, b0, b1) \
    asm volatile("mma.sync.aligned.m16n8k16.row.col.f32.bf16.bf16.f32 " \
        "{%0,%1,%2,%3},{%4,%5,%6,%7},{%8,%9},{%0,%1,%2,%3};" \
        : "+f"((C)[0]), "+f"((C)[1]), "+f"((C)[2]), "+f"((C)[3]) \
        : "r"((A)[0]), "r"((A)[1]), "r"((A)[2]), "r"((A)[3]), "r"(b0), "r"(b1))

#define MMA_BF16_K8(C, A, B) \
    asm volatile("mma.sync.aligned.m16n8k8.row.col.f32.bf16.bf16.f32 " \
        "{%0,%1,%2,%3},{%4,%5},{%6},{%0,%1,%2,%3};" \
        : "+f"((C)[0]), "+f"((C)[1]), "+f"((C)[2]), "+f"((C)[3]) \
        : "r"((A)[0]), "r"((A)[1]), "r"(B))

// ---------------------------------------------------------------------------
// bf16 hi/lo pack
// ---------------------------------------------------------------------------
__device__ __forceinline__ void pack8(const float* v, uint4* hi4, uint4* lo4) {
    uint32_t hi[4], lo[4];
#pragma unroll
    for (int i = 0; i < 4; i++) {
        __nv_bfloat16 h0 = __float2bfloat16(v[2 * i]);
        __nv_bfloat16 h1 = __float2bfloat16(v[2 * i + 1]);
        __nv_bfloat16 l0 = __float2bfloat16(v[2 * i] - __bfloat162float(h0));
        __nv_bfloat16 l1 = __float2bfloat16(v[2 * i + 1] - __bfloat162float(h1));
        hi[i] = ((uint32_t)__bfloat16_as_ushort(h1) << 16) | __bfloat16_as_ushort(h0);
        lo[i] = ((uint32_t)__bfloat16_as_ushort(l1) << 16) | __bfloat16_as_ushort(l0);
    }
    *hi4 = make_uint4(hi[0], hi[1], hi[2], hi[3]);
    *lo4 = make_uint4(lo[0], lo[1], lo[2], lo[3]);
}

// ---------------------------------------------------------------------------
// Kernel 0 (prep): W conv + skin-weight conv + SLICED jpart partials.
// ---------------------------------------------------------------------------
__global__ void __launch_bounds__(256) k_prep(const float* __restrict__ pd,
                                              const float* __restrict__ sd,
                                              const float* __restrict__ vt,
                                              const float* __restrict__ wts,
                                              const float* __restrict__ Jreg) {
    int bid = blockIdx.x;
    int t = threadIdx.x;
    if (bid < WBLK2) {
        int idx = bid * 256 + t;          // over M_WPAD*32
        int m = idx >> 5;
        int k0 = (idx & 31) * 8;
        float v[8];
#pragma unroll
        for (int i = 0; i < 8; i++) {
            int k = k0 + i;
            float x = 0.f;
            if (m < M_TOT) {
                if (k < 207)       x = pd[(size_t)m * 207 + k];
                else if (k < 217)  x = sd[(size_t)m * 10 + (k - 207)];
                else if (k == 217) x = vt[m];
            }
            v[i] = x;
        }
        uint4 hi4, lo4;
        pack8(v, &hi4, &lo4);
        size_t off = (size_t)idx * 8;
        *(uint4*)(g_Whi + off) = hi4;
        *(uint4*)(g_Wlo + off) = lo4;
    } else if (bid < WBLK2 + WSBLK) {
        int idx = (bid - WBLK2) * 256 + t;  // over NVP*4
        int vv = idx >> 2;
        int k0 = (idx & 3) * 8;
        float v[8];
#pragma unroll
        for (int i = 0; i < 8; i++) {
            int k = k0 + i;
            v[i] = (vv < NV && k < 24) ? wts[vv * 24 + k] : 0.f;
        }
        uint4 hi4, lo4;
        pack8(v, &hi4, &lo4);
        size_t off = (size_t)idx * 8;
        *(uint4*)(g_WShi + off) = hi4;
        *(uint4*)(g_WSlo + off) = lo4;
    } else {
        // sliced jpart: stage vt+sd for 256 verts once, warps do 3 joints each
        __shared__ float vals[256][34];
        int sl = bid - WBLK2 - WSBLK;
        int vbase = sl * 256;
        int v = vbase + t;
        if (v < NV) {
            vals[t][0] = vt[v * 3 + 0];
            vals[t][1] = vt[v * 3 + 1];
            vals[t][2] = vt[v * 3 + 2];
            const float* sp = sd + (size_t)v * 30;
#pragma unroll
            for (int e = 0; e < 30; e++) vals[t][3 + e] = sp[e];
        } else {
#pragma unroll
            for (int e = 0; e < 33; e++) vals[t][e] = 0.f;
        }
        __syncthreads();

        int w = t >> 5, lane = t & 31;
        for (int jj = 0; jj < 3; jj++) {
            int j = w * 3 + jj;
            float acc[33];
#pragma unroll
            for (int e = 0; e < 33; e++) acc[e] = 0.f;
            for (int vl = lane; vl < 256; vl += 32) {
                int vg = vbase + vl;
                float r = (vg < NV) ? Jreg[j * NV + vg] : 0.f;
#pragma unroll
                for (int e = 0; e < 33; e++) acc[e] += r * vals[vl][e];
            }
#pragma unroll
            for (int e = 0; e < 33; e++) {
#pragma unroll
                for (int o = 16; o > 0; o >>= 1)
                    acc[e] += __shfl_xor_sync(0xffffffffu, acc[e], o);
            }
            if (lane == 0) {
#pragma unroll
                for (int e = 0; e < 33; e++)
                    g_Jpart[(j * NSL + sl) * 33 + e] = acc[e];
            }
        }
    }
}

__global__ void k_jreduce() {
    int t = threadIdx.x;
    if (t < NJ * 33) {
        int j = t / 33, e = t % 33;
        float r = 0.f;
#pragma unroll
        for (int s = 0; s < NSL; s++) r += g_Jpart[(j * NSL + s) * 33 + e];
        if (e < 3) g_Jv[j * 3 + e] = r;
        else       g_Js[j * 30 + (e - 3)] = r;
    }
}

// ---------------------------------------------------------------------------
// Kernel: Rodrigues + kinematic chain + G2 + jtr; writes X as bf16 hi/lo.
// ---------------------------------------------------------------------------
__device__ __forceinline__ void wr_xsplit(int idx, float v) {
    __nv_bfloat16 h = __float2bfloat16(v);
    g_Xhi[idx] = h;
    g_Xlo[idx] = __float2bfloat16(v - __bfloat162float(h));
}

__global__ void k_pose(const float* __restrict__ pose,
                       const float* __restrict__ betas,
                       const float* __restrict__ trans,
                       float* __restrict__ jtr) {
    int b = blockIdx.x, t = threadIdx.x;
    __shared__ float Rsh[NJ][9];
    __shared__ float Jsh[NJ][3];
    __shared__ float G[NJ][16];

    if (t < NJ) {
        float ax = pose[b * 72 + t * 3 + 0];
        float ay = pose[b * 72 + t * 3 + 1];
        float az = pose[b * 72 + t * 3 + 2];
        float th = sqrtf(ax * ax + ay * ay + az * az + 1e-8f);
        float inv = 1.f / th;
        float kx = ax * inv, ky = ay * inv, kz = az * inv;
        float ct = cosf(th), st = sinf(th);
        float K[9] = {0.f, -kz, ky, kz, 0.f, -kx, -ky, kx, 0.f};
        float Rm[9];
#pragma unroll
        for (int r = 0; r < 3; r++) {
#pragma unroll
            for (int c = 0; c < 3; c++) {
                float k2 = K[r * 3 + 0] * K[0 + c] + K[r * 3 + 1] * K[3 + c] + K[r * 3 + 2] * K[6 + c];
                Rm[r * 3 + c] = ((r == c) ? 1.f : 0.f) + st * K[r * 3 + c] + (1.f - ct) * k2;
            }
        }
#pragma unroll
        for (int e = 0; e < 9; e++) Rsh[t][e] = Rm[e];
        if (t >= 1) {
#pragma unroll
            for (int e = 0; e < 9; e++)
                wr_xsplit(b * KP + (t - 1) * 9 + e,
                          Rm[e] - ((e == 0 || e == 4 || e == 8) ? 1.f : 0.f));
        }
#pragma unroll
        for (int c = 0; c < 3; c++) {
            float v = g_Jv[t * 3 + c];
#pragma unroll
            for (int s = 0; s < 10; s++)
                v += g_Js[t * 30 + c * 10 + s] * betas[b * 10 + s];
            Jsh[t][c] = v;
        }
    }
    if (t < 17) {
        float v = (t < 10) ? betas[b * 10 + t] : ((t == 10) ? 1.f : 0.f);
        wr_xsplit(b * KP + 207 + t, v);
    }
    {
        int k = 224 + t;                 // zero tail 224..255
        g_Xhi[b * KP + k] = __float2bfloat16(0.f);
        g_Xlo[b * KP + k] = __float2bfloat16(0.f);
    }
    __syncwarp();

    if (t < 16) {
        int r = t >> 2, c = t & 3;
        G[0][t] = (r < 3) ? ((c < 3) ? Rsh[0][r * 3 + c] : Jsh[0][r])
                          : ((c == 3) ? 1.f : 0.f);
    }
    __syncwarp();

    for (int i = 1; i < NJ; i++) {
        int p = c_par[i];
        float v = 0.f;
        if (t < 16) {
            int r = t >> 2, c = t & 3;
            float l0, l1, l2, l3;
            if (c < 3) {
                l0 = Rsh[i][c]; l1 = Rsh[i][3 + c]; l2 = Rsh[i][6 + c]; l3 = 0.f;
            } else {
                l0 = Jsh[i][0] - Jsh[p][0];
                l1 = Jsh[i][1] - Jsh[p][1];
                l2 = Jsh[i][2] - Jsh[p][2];
                l3 = 1.f;
            }
            v = G[p][r * 4 + 0] * l0 + G[p][r * 4 + 1] * l1 +
                G[p][r * 4 + 2] * l2 + G[p][r * 4 + 3] * l3;
        }
        __syncwarp();
        if (t < 16) G[i][t] = v;
        __syncwarp();
    }

    if (t < NJ) {
        const float* g = G[t];
        float jx = Jsh[t][0], jy = Jsh[t][1], jz = Jsh[t][2];
        float* o = g_G2 + (size_t)(b * NJ + t) * 12;
        o[0] = g[0];  o[1] = g[1];  o[2]  = g[2];
        o[3] = g[3] - (g[0] * jx + g[1] * jy + g[2] * jz);
        o[4] = g[4];  o[5] = g[5];  o[6]  = g[6];
        o[7] = g[7] - (g[4] * jx + g[5] * jy + g[6] * jz);
        o[8] = g[8];  o[9] = g[9];  o[10] = g[10];
        o[11] = g[11] - (g[8] * jx + g[9] * jy + g[10] * jz);
        jtr[b * 72 + t * 3 + 0] = g[3]  + trans[b * 3 + 0];
        jtr[b * 72 + t * 3 + 1] = g[7]  + trans[b * 3 + 1];
        jtr[b * 72 + t * 3 + 2] = g[11] + trans[b * 3 + 2];
    }
}

// ---------------------------------------------------------------------------
// Kernel: tensor-core GEMM, bf16 3-mult hi/lo split, cp.async 2-stage.
// ---------------------------------------------------------------------------
__global__ void __launch_bounds__(256, 2) k_mma() {
    extern __shared__ __align__(1024) char dsm[];
    uint32_t base = smem_u32(dsm);
    uint32_t sA[2] = { base, base + 16384 };
    uint32_t sB[2] = { base + 32768, base + 49152 };
    int tid = threadIdx.x;
    int w = tid >> 5, lane = tid & 31;
    int m0 = blockIdx.x * BN;
    int by = blockIdx.y;
    int wm = (w >> 1) * 32;
    int wn = (w & 1) * 64;

    float c[2][8][4];
#pragma unroll
    for (int mi = 0; mi < 2; mi++)
#pragma unroll
        for (int ni = 0; ni < 8; ni++)
#pragma unroll
            for (int e = 0; e < 4; e++) c[mi][ni][e] = 0.f;

    int row = tid >> 1, half = tid & 1;
    const __nv_bfloat16* gAh = g_Xhi + (size_t)(by * BM + row) * KP + half * 16;
    const __nv_bfloat16* gAl = g_Xlo + (size_t)(by * BM + row) * KP + half * 16;
    const __nv_bfloat16* gBh = g_Whi + (size_t)(m0 + row) * KP + half * 16;
    const __nv_bfloat16* gBl = g_Wlo + (size_t)(m0 + row) * KP + half * 16;
    uint32_t oA = row * 128 + half * 32;
    uint32_t d0 = SWZ(oA), d1 = SWZ(oA + 16), d2 = SWZ(oA + 64), d3 = SWZ(oA + 80);

#define ISSUE_CHUNK(kk, st) do { \
        CPASYNC16(sA[st] + d0, gAh + (kk)); \
        CPASYNC16(sA[st] + d1, gAh + (kk) + 8); \
        CPASYNC16(sA[st] + d2, gAl + (kk)); \
        CPASYNC16(sA[st] + d3, gAl + (kk) + 8); \
        CPASYNC16(sB[st] + d0, gBh + (kk)); \
        CPASYNC16(sB[st] + d1, gBh + (kk) + 8); \
        CPASYNC16(sB[st] + d2, gBl + (kk)); \
        CPASYNC16(sB[st] + d3, gBl + (kk) + 8); \
        CPCOMMIT(); \
    } while (0)

    uint32_t lA[2][2], lB[2][4];
#pragma unroll
    for (int ks = 0; ks < 2; ks++) {
#pragma unroll
        for (int mi = 0; mi < 2; mi++)
            lA[ks][mi] = (uint32_t)(wm + mi * 16 + (lane & 15)) * 128
                       + ks * 32 + (lane >> 4) * 16;
#pragma unroll
        for (int np = 0; np < 4; np++)
            lB[ks][np] = (uint32_t)(wn + np * 16 + ((lane >> 4) & 1) * 8 + (lane & 7)) * 128
                       + ks * 32 + ((lane >> 3) & 1) * 16;
    }

    ISSUE_CHUNK(0, 0);
    ISSUE_CHUNK(32, 1);
    CPWAIT(1);
    __syncthreads();

    for (int cc = 0; cc < NCH; cc++) {
        int cur = cc & 1;
#pragma unroll
        for (int ks = 0; ks < 2; ks++) {
            uint32_t Ah[2][4], Al[2][4];
#pragma unroll
            for (int mi = 0; mi < 2; mi++) {
                LDSM_X4(Ah[mi], sA[cur] + SWZ(lA[ks][mi]));
                LDSM_X4(Al[mi], sA[cur] + SWZ(lA[ks][mi] + 64));
            }
#pragma unroll
            for (int np = 0; np < 4; np++) {
                uint32_t rh[4], rl[4];
                LDSM_X4(rh, sB[cur] + SWZ(lB[ks][np]));
                LDSM_X4(rl, sB[cur] + SWZ(lB[ks][np] + 64));
#pragma unroll
                for (int mi = 0; mi < 2; mi++) {
                    MMA_BF16P(c[mi][2 * np],     Ah[mi], rh[0], rh[1]);
                    MMA_BF16P(c[mi][2 * np],     Ah[mi], rl[0], rl[1]);
                    MMA_BF16P(c[mi][2 * np],     Al[mi], rh[0], rh[1]);
                    MMA_BF16P(c[mi][2 * np + 1], Ah[mi], rh[2], rh[3]);
                    MMA_BF16P(c[mi][2 * np + 1], Ah[mi], rl[2], rl[3]);
                    MMA_BF16P(c[mi][2 * np + 1], Al[mi], rh[2], rh[3]);
                }
            }
        }
        __syncthreads();
        if (cc + 2 < NCH) {
            ISSUE_CHUNK((cc + 2) * 32, cur);
            CPWAIT(1);
        } else {
            CPWAIT(0);
        }
        if (cc + 1 < NCH) __syncthreads();
    }

    int gr = lane >> 2, tc = lane & 3;
#pragma unroll
    for (int mi = 0; mi < 2; mi++) {
        int b = by * BM + wm + mi * 16 + gr;
        float* rowp = g_vposed + (size_t)b * M_PAD;
#pragma unroll
        for (int ni = 0; ni < 8; ni++) {
            int m = m0 + wn + ni * 8 + tc * 2;
            if (m < M_TOT) {
                *(float2*)(rowp + m) = make_float2(c[mi][ni][0], c[mi][ni][1]);
                *(float2*)(rowp + (size_t)8 * M_PAD + m) = make_float2(c[mi][ni][2], c[mi][ni][3]);
            }
        }
    }
}

// ---------------------------------------------------------------------------
// Kernel: tensor-core skinning, smem-staging epilogue, NB=16 (R13's measured
// best: 99.97us).
// ---------------------------------------------------------------------------
__global__ void __launch_bounds__(256, 3) k_skinT(const float* __restrict__ trans,
                                                  float* __restrict__ out) {
    __shared__ __align__(1024) float sBuf[8192];    // 32 KB: Wh|Wl, reused as T
    __shared__ uint32_t sBpk[8 * 576];              // 18.4 KB packed B frags
    char* sWh = (char*)sBuf;
    char* sWl = (char*)sBuf + 16384;
    float* Tsm = sBuf;                              // [2][256][12] = 24 KB

    uint32_t swh = smem_u32(sWh), swl = smem_u32(sWl);
    int tid = threadIdx.x;
    int w = tid >> 5, lane = tid & 31;
    int b0 = blockIdx.x * NB;
    int vbase = blockIdx.y * 256;

    {
        const uint4* srch = (const uint4*)(g_WShi + (size_t)(vbase + tid) * 32);
        const uint4* srcl = (const uint4*)(g_WSlo + (size_t)(vbase + tid) * 32);
        uint32_t so = tid * 64;
#pragma unroll
        for (int q = 0; q < 4; q++) {
            sts128(swh + SWZ64(so + q * 16), srch[q]);
            sts128(swl + SWZ64(so + q * 16), srcl[q]);
        }
    }

    for (int i = 0; i < 18; i++) {
        int idx = tid + i * 256;
        int bl = idx & 31;
        int rest = idx >> 5;                 // 0..143
        int wI = rest % 3;
        int hl = (rest / 3) % 2;
        int nt = (rest / 6) % 3;
        int pi = rest / 18;                  // 0..7
        int n = nt * 8 + (bl >> 2);          // 0..23
        int bi = pi * 2 + (n >= 12 ? 1 : 0);
        int col = (n >= 12) ? n - 12 : n;
        int j0 = (wI == 0) ? (bl & 3) * 2
               : (wI == 1) ? (bl & 3) * 2 + 8
                           : 16 + (bl & 3) * 2;
        const float* g = g_G2 + ((size_t)(b0 + bi) * NJ + j0) * 12 + col;
        float v0 = g[0], v1 = g[12];
        __nv_bfloat16 h0 = __float2bfloat16(v0);
        __nv_bfloat16 h1 = __float2bfloat16(v1);
        if (hl) {
            h0 = __float2bfloat16(v0 - __bfloat162float(h0));
            h1 = __float2bfloat16(v1 - __bfloat162float(h1));
        }
        sBpk[idx] = ((uint32_t)__bfloat16_as_ushort(h1) << 16) | __bfloat16_as_ushort(h0);
    }
    __syncthreads();

    uint32_t Ah16[2][4], Al16[2][4], Ah8[2][2], Al8[2][2];
#pragma unroll
    for (int mt = 0; mt < 2; mt++) {
        uint32_t o16 = (uint32_t)(w * 32 + mt * 16 + (lane & 15)) * 64 + (lane >> 4) * 16;
        LDSM_X4(Ah16[mt], swh + SWZ64(o16));
        LDSM_X4(Al16[mt], swl + SWZ64(o16));
        uint32_t o8 = (uint32_t)(w * 32 + mt * 16 + (lane & 15)) * 64 + 32;
        LDSM_X2(Ah8[mt], swh + SWZ64(o8));
        LDSM_X2(Al8[mt], swl + SWZ64(o8));
    }
    __syncthreads();

    int gr = lane >> 2, tc = lane & 3;

    for (int pi = 0; pi < NB / 2; pi++) {
        float c[2][3][4];
#pragma unroll
        for (int mt = 0; mt < 2; mt++)
#pragma unroll
            for (int nt = 0; nt < 3; nt++)
#pragma unroll
                for (int e = 0; e < 4; e++) c[mt][nt][e] = 0.f;

        const uint32_t* bp = sBpk + pi * 576;
#pragma unroll
        for (int nt = 0; nt < 3; nt++) {
            uint32_t bh16[2] = { bp[(nt * 6 + 0) * 32 + lane], bp[(nt * 6 + 1) * 32 + lane] };
            uint32_t bh8     =   bp[(nt * 6 + 2) * 32 + lane];
            uint32_t bl16[2] = { bp[(nt * 6 + 3) * 32 + lane], bp[(nt * 6 + 4) * 32 + lane] };
            uint32_t bl8     =   bp[(nt * 6 + 5) * 32 + lane];
#pragma unroll
            for (int mt = 0; mt < 2; mt++) {
                MMA_BF16(c[mt][nt], Ah16[mt], bh16);
                MMA_BF16(c[mt][nt], Ah16[mt], bl16);
                MMA_BF16(c[mt][nt], Al16[mt], bh16);
                MMA_BF16_K8(c[mt][nt], Ah8[mt], bh8);
                MMA_BF16_K8(c[mt][nt], Ah8[mt], bl8);
                MMA_BF16_K8(c[mt][nt], Al8[mt], bh8);
            }
        }

#pragma unroll
        for (int mt = 0; mt < 2; mt++) {
            int v0 = w * 32 + mt * 16 + gr;
#pragma unroll
            for (int nt = 0; nt < 3; nt++) {
                int n0 = nt * 8 + tc * 2;          // even, 0..22
                int s = (n0 >= 12) ? 1 : 0;
                int col = n0 - s * 12;
                float* dst = &Tsm[(size_t)(s * 256 + v0) * 12 + col];
                *(float2*)dst = make_float2(c[mt][nt][0], c[mt][nt][1]);
                *(float2*)(dst + 8 * 12) = make_float2(c[mt][nt][2], c[mt][nt][3]);
            }
        }
        __syncthreads();

#pragma unroll
        for (int s = 0; s < 2; s++) {
            int b = b0 + pi * 2 + s;
            int v = vbase + tid;
            if (v < NV) {
                const float* Tq = &Tsm[(size_t)(s * 256 + tid) * 12];
                float4 T0 = *(const float4*)(Tq);
                float4 T1 = *(const float4*)(Tq + 4);
                float4 T2 = *(const float4*)(Tq + 8);
                const float* pp = g_vposed + (size_t)b * M_PAD + (size_t)v * 3;
                float px = pp[0], py = pp[1], pz = pp[2];
                float trx = trans[b * 3 + 0];
                float try_ = trans[b * 3 + 1];
                float trz = trans[b * 3 + 2];
                size_t o = (size_t)b * M_TOT + (size_t)v * 3;
                out[o + 0] = T0.x * px + T0.y * py + T0.z * pz + T0.w + trx;
                out[o + 1] = T1.x * px + T1.y * py + T1.z * pz + T1.w + try_;
                out[o + 2] = T2.x * px + T2.y * py + T2.z * pz + T2.w + trz;
            }
        }
        __syncthreads();
    }
}

// ---------------------------------------------------------------------------
extern "C" void kernel_launch(void* const* d_in, const int* in_sizes, int n_in,
                              void* d_out, int out_size) {
    const float* pose  = (const float*)d_in[0];  // [1024,72]
    const float* betas = (const float*)d_in[1];  // [1024,10]
    const float* trans = (const float*)d_in[2];  // [1024,3]
    const float* vt    = (const float*)d_in[3];  // [6890,3]
    const float* sd    = (const float*)d_in[4];  // [6890,3,10]
    const float* pd    = (const float*)d_in[5];  // [6890,3,207]
    const float* jreg  = (const float*)d_in[6];  // [24,6890]
    const float* wts   = (const float*)d_in[7];  // [6890,24]
    float* out = (float*)d_out;
    float* jtr = out + (size_t)BATCH * M_TOT;

    cudaFuncSetAttribute(k_mma, cudaFuncAttributeMaxDynamicSharedMemorySize, SMEM_MMA);

    k_prep<<<WBLK2 + WSBLK + NSL, 256>>>(pd, sd, vt, wts, jreg);           // 0
    k_jreduce<<<1, 792>>>();                                               // 1
    k_pose<<<BATCH, 32>>>(pose, betas, trans, jtr);                        // 2
    k_mma<<<dim3(M_WPAD / BN, BATCH / BM), 256, SMEM_MMA>>>();             // 3
    k_skinT<<<dim3(BATCH / NB, NVP / 256), 256>>>(trans, out);             // 4
}